// round 2
// baseline (speedup 1.0000x reference)
#include <cuda_runtime.h>
#include <cuda_fp16.h>

// Problem constants
#define BB 256    // batch
#define TT 512    // timesteps
#define FF 64     // input features

// ---------------------------------------------------------------------------
// Device scratch (no cudaMalloc allowed) — ~640MB total
// ---------------------------------------------------------------------------
__device__ float g_zx1[TT * BB * 512];   // [T,B,4*128]
__device__ float g_h1 [TT * BB * 128];   // [T,B,128]
__device__ float g_zx2[TT * BB * 256];   // [T,B,4*64]
__device__ float g_h2 [TT * BB * 64];    // [T,B,64]
__device__ float g_zx3[TT * BB * 256];   // [T,B,4*64]
__device__ float g_h3 [BB * 64];         // last-step hidden of layer 3

// ---------------------------------------------------------------------------
// Projection GEMM:  C[m][n] = A_row(m) . W[:,n] + bias[n]
//   m = t*B + b  (zx layout [T,B,4u])
//   GATHER=true  : A = x with layout [B,T,F]  -> row ptr = x + (b*T + t)*K
//   GATHER=false : A layout [T,B,K] (same m order) -> row ptr = A + m*K
// Tile 128x128, BK=8, 256 threads, 8x8 microtile.
// ---------------------------------------------------------------------------
template<int K, int N, bool GATHER>
__global__ __launch_bounds__(256) void proj_gemm(
    const float* __restrict__ A, const float* __restrict__ W,
    const float* __restrict__ bias, float* __restrict__ C)
{
    constexpr int BM = 128, BN = 128, BK = 8;
    __shared__ float As[BK][BM];
    __shared__ float Ws[BK][BN];

    const int tid = threadIdx.x;
    const int m0  = blockIdx.x * BM;
    const int n0  = blockIdx.y * BN;

    // A tile loading: 128 rows x 8 k, 2 threads/row, float4 each
    const int arow = tid >> 1;
    const int acol = (tid & 1) << 2;
    // W tile loading: 8 k-rows x 128 cols, float4 each
    const int wk = tid >> 5;
    const int wn = (tid & 31) << 2;

    const float* a_src;
    {
        int mrow = m0 + arow;
        if (GATHER) {
            int b = mrow & (BB - 1);
            int t = mrow >> 8;            // mrow / 256
            a_src = A + ((long)b * TT + t) * K + acol;
        } else {
            a_src = A + (long)mrow * K + acol;
        }
    }
    const float* w_src = W + (long)wk * N + n0 + wn;

    const int tx = tid & 15;
    const int ty = tid >> 4;

    float acc[8][8];
#pragma unroll
    for (int i = 0; i < 8; i++)
#pragma unroll
        for (int j = 0; j < 8; j++) acc[i][j] = 0.f;

    for (int kt = 0; kt < K; kt += BK) {
        float4 av = *reinterpret_cast<const float4*>(a_src + kt);
        float4 wv = *reinterpret_cast<const float4*>(w_src + (long)kt * N);
        As[acol + 0][arow] = av.x;
        As[acol + 1][arow] = av.y;
        As[acol + 2][arow] = av.z;
        As[acol + 3][arow] = av.w;
        *reinterpret_cast<float4*>(&Ws[wk][wn]) = wv;
        __syncthreads();

#pragma unroll
        for (int k = 0; k < BK; k++) {
            float4 a0 = *reinterpret_cast<const float4*>(&As[k][ty * 8]);
            float4 a1 = *reinterpret_cast<const float4*>(&As[k][ty * 8 + 4]);
            float4 b0 = *reinterpret_cast<const float4*>(&Ws[k][tx * 8]);
            float4 b1 = *reinterpret_cast<const float4*>(&Ws[k][tx * 8 + 4]);
            float ar[8] = {a0.x, a0.y, a0.z, a0.w, a1.x, a1.y, a1.z, a1.w};
            float br[8] = {b0.x, b0.y, b0.z, b0.w, b1.x, b1.y, b1.z, b1.w};
#pragma unroll
            for (int i = 0; i < 8; i++)
#pragma unroll
                for (int j = 0; j < 8; j++)
                    acc[i][j] += ar[i] * br[j];
        }
        __syncthreads();
    }

    float bb[8];
#pragma unroll
    for (int j = 0; j < 8; j++) bb[j] = bias[n0 + tx * 8 + j];

#pragma unroll
    for (int i = 0; i < 8; i++) {
        long m = m0 + ty * 8 + i;
        float4 o0, o1;
        o0.x = acc[i][0] + bb[0]; o0.y = acc[i][1] + bb[1];
        o0.z = acc[i][2] + bb[2]; o0.w = acc[i][3] + bb[3];
        o1.x = acc[i][4] + bb[4]; o1.y = acc[i][5] + bb[5];
        o1.z = acc[i][6] + bb[6]; o1.w = acc[i][7] + bb[7];
        *reinterpret_cast<float4*>(&C[m * N + n0 + tx * 8])     = o0;
        *reinterpret_cast<float4*>(&C[m * N + n0 + tx * 8 + 4]) = o1;
    }
}

// ---------------------------------------------------------------------------
// Persistent recurrent LSTM kernel.
//   Each CTA owns BS batch rows, loops T steps.
//   Weights in SMEM (fp16 packed for U=128 to fit; fp32 for U=64).
//   zx prefetched one step ahead into registers.
// Gate order [i,f,g,o]; c = sig(f)*c + sig(i)*relu(g); h = sig(o)*relu(c).
// ---------------------------------------------------------------------------
__device__ __forceinline__ float sigf(float x) {
    return 1.0f / (1.0f + __expf(-x));
}

template<int U, int BS, bool HALFW, bool WRITE_ALL>
__global__ __launch_bounds__(256) void lstm_rec(
    const float* __restrict__ zx, const float* __restrict__ Uw,
    float* __restrict__ h_out)
{
    constexpr int G   = 4 * U;
    constexpr int NT  = 256;
    constexpr int GPT = G / NT;               // gate cols per thread (2 or 1)
    constexpr int WBYTES = HALFW ? U * G * 2 : U * G * 4;

    extern __shared__ char smem_raw[];
    float* h_s = reinterpret_cast<float*>(smem_raw + WBYTES); // [2][BS][U]
    float* z_s = h_s + 2 * BS * U;                            // [BS][G]

    const int tid = threadIdx.x;
    const int b0  = blockIdx.x * BS;
    const int gc  = GPT * tid;                // base gate column (adjacent cols)

    // --- load weights to SMEM ---
    if (HALFW) {
        __half2* Wp = reinterpret_cast<__half2*>(smem_raw);   // [U/2][G], .x=even k
        for (int idx = tid; idx < (U / 2) * G; idx += NT) {
            int k2 = idx / G;
            int g  = idx - k2 * G;
            Wp[idx] = __floats2half2_rn(Uw[(2 * k2) * G + g],
                                        Uw[(2 * k2 + 1) * G + g]);
        }
    } else {
        float* Wf = reinterpret_cast<float*>(smem_raw);        // [U][G]
        for (int idx = tid; idx < U * G; idx += NT) Wf[idx] = Uw[idx];
    }
    for (int idx = tid; idx < 2 * BS * U; idx += NT) h_s[idx] = 0.f;
    __syncthreads();

    const int cb = tid / U;        // combine-phase batch row
    const int cj = tid % U;        // combine-phase hidden unit
    float creg = 0.f;

    // initial zx prefetch (t = 0)
    float zpre[GPT][BS];
#pragma unroll
    for (int q = 0; q < GPT; q++)
#pragma unroll
        for (int b = 0; b < BS; b++)
            zpre[q][b] = zx[(b0 + b) * G + gc + q];

    int cur = 0;
#pragma unroll 1
    for (int t = 0; t < TT; t++) {
        float acc[GPT][BS];
#pragma unroll
        for (int q = 0; q < GPT; q++)
#pragma unroll
            for (int b = 0; b < BS; b++) acc[q][b] = zpre[q][b];

        if (t + 1 < TT) {
#pragma unroll
            for (int q = 0; q < GPT; q++)
#pragma unroll
                for (int b = 0; b < BS; b++)
                    zpre[q][b] = zx[((t + 1) * BB + b0 + b) * G + gc + q];
        }

        const float* hc = h_s + cur * BS * U;

        if (HALFW) {
            const __half2* Wp = reinterpret_cast<const __half2*>(smem_raw);
#pragma unroll
            for (int k4 = 0; k4 < U / 4; k4++) {
                float4 hv[BS];
#pragma unroll
                for (int b = 0; b < BS; b++)
                    hv[b] = *reinterpret_cast<const float4*>(hc + b * U + 4 * k4);
#pragma unroll
                for (int kk = 0; kk < 2; kk++) {
                    const int k2 = 2 * k4 + kk;
                    float2 wcol[GPT];
#pragma unroll
                    for (int q = 0; q < GPT; q++)
                        wcol[q] = __half22float2(Wp[k2 * G + gc + q]);
#pragma unroll
                    for (int b = 0; b < BS; b++) {
                        float ha = kk ? hv[b].z : hv[b].x;
                        float hb = kk ? hv[b].w : hv[b].y;
#pragma unroll
                        for (int q = 0; q < GPT; q++)
                            acc[q][b] += ha * wcol[q].x + hb * wcol[q].y;
                    }
                }
            }
        } else {
            const float* Wf = reinterpret_cast<const float*>(smem_raw);
#pragma unroll
            for (int k4 = 0; k4 < U / 4; k4++) {
                float4 hv[BS];
#pragma unroll
                for (int b = 0; b < BS; b++)
                    hv[b] = *reinterpret_cast<const float4*>(hc + b * U + 4 * k4);
                float w0[GPT], w1[GPT], w2[GPT], w3[GPT];
#pragma unroll
                for (int q = 0; q < GPT; q++) {
                    w0[q] = Wf[(4 * k4 + 0) * G + gc + q];
                    w1[q] = Wf[(4 * k4 + 1) * G + gc + q];
                    w2[q] = Wf[(4 * k4 + 2) * G + gc + q];
                    w3[q] = Wf[(4 * k4 + 3) * G + gc + q];
                }
#pragma unroll
                for (int b = 0; b < BS; b++)
#pragma unroll
                    for (int q = 0; q < GPT; q++)
                        acc[q][b] += hv[b].x * w0[q] + hv[b].y * w1[q]
                                   + hv[b].z * w2[q] + hv[b].w * w3[q];
            }
        }

        // publish z
#pragma unroll
        for (int b = 0; b < BS; b++)
#pragma unroll
            for (int q = 0; q < GPT; q++)
                z_s[b * G + gc + q] = acc[q][b];
        __syncthreads();

        // gate combine + state update
        if (tid < BS * U) {
            float zi = z_s[cb * G + cj];
            float zf = z_s[cb * G + U + cj];
            float zg = z_s[cb * G + 2 * U + cj];
            float zo = z_s[cb * G + 3 * U + cj];
            float ig = sigf(zi);
            float fg = sigf(zf);
            float gg = fmaxf(zg, 0.f);
            float og = sigf(zo);
            creg = fg * creg + ig * gg;
            float h = og * fmaxf(creg, 0.f);
            h_s[(cur ^ 1) * BS * U + cb * U + cj] = h;
            if (WRITE_ALL) {
                h_out[((long)t * BB + b0 + cb) * U + cj] = h;
            } else if (t == TT - 1) {
                h_out[(b0 + cb) * U + cj] = h;
            }
        }
        __syncthreads();
        cur ^= 1;
    }
}

// ---------------------------------------------------------------------------
// Dense head: out[b] = relu(h3[b] @ Wd1 + bd1) @ Wd2 + bd2
// ---------------------------------------------------------------------------
__global__ __launch_bounds__(256) void dense_kernel(
    const float* __restrict__ h3, const float* __restrict__ Wd1,
    const float* __restrict__ bd1, const float* __restrict__ Wd2,
    const float* __restrict__ bd2, float* __restrict__ out)
{
    __shared__ float w1[64 * 32];
    __shared__ float w2[32];
    __shared__ float b1s[32];
    const int tid = threadIdx.x;
    for (int i = tid; i < 64 * 32; i += 256) w1[i] = Wd1[i];
    if (tid < 32) { w2[tid] = Wd2[tid]; b1s[tid] = bd1[tid]; }
    __syncthreads();

    float hr[64];
#pragma unroll
    for (int k4 = 0; k4 < 16; k4++)
        *reinterpret_cast<float4*>(&hr[4 * k4]) =
            *reinterpret_cast<const float4*>(&h3[tid * 64 + 4 * k4]);

    float o = bd2[0];
#pragma unroll 4
    for (int j = 0; j < 32; j++) {
        float d = b1s[j];
#pragma unroll
        for (int k = 0; k < 64; k++) d += hr[k] * w1[k * 32 + j];
        o += fmaxf(d, 0.f) * w2[j];
    }
    out[tid] = o;
}

// ---------------------------------------------------------------------------
// Launcher
// ---------------------------------------------------------------------------
extern "C" void kernel_launch(void* const* d_in, const int* in_sizes, int n_in,
                              void* d_out, int out_size)
{
    const float* x   = (const float*)d_in[0];
    const float* W1  = (const float*)d_in[1];
    const float* Uw1 = (const float*)d_in[2];
    const float* b1  = (const float*)d_in[3];
    const float* W2  = (const float*)d_in[4];
    const float* Uw2 = (const float*)d_in[5];
    const float* b2  = (const float*)d_in[6];
    const float* W3  = (const float*)d_in[7];
    const float* Uw3 = (const float*)d_in[8];
    const float* b3  = (const float*)d_in[9];
    const float* Wd1 = (const float*)d_in[10];
    const float* bd1 = (const float*)d_in[11];
    const float* Wd2 = (const float*)d_in[12];
    const float* bd2 = (const float*)d_in[13];

    float *zx1, *h1, *zx2, *h2, *zx3, *h3;
    cudaGetSymbolAddress((void**)&zx1, g_zx1);
    cudaGetSymbolAddress((void**)&h1,  g_h1);
    cudaGetSymbolAddress((void**)&zx2, g_zx2);
    cudaGetSymbolAddress((void**)&h2,  g_h2);
    cudaGetSymbolAddress((void**)&zx3, g_zx3);
    cudaGetSymbolAddress((void**)&h3,  g_h3);

    constexpr int SMEM1 = 128 * 512 * 2 + 2 * 2 * 128 * 4 + 2 * 512 * 4; // 137216
    constexpr int SMEM2 = 64 * 256 * 4 + 2 * 2 * 64 * 4 + 2 * 256 * 4;  // 68608

    cudaFuncSetAttribute((const void*)lstm_rec<128, 2, true,  true>,
                         cudaFuncAttributeMaxDynamicSharedMemorySize, SMEM1);
    cudaFuncSetAttribute((const void*)lstm_rec<64,  2, false, true>,
                         cudaFuncAttributeMaxDynamicSharedMemorySize, SMEM2);
    cudaFuncSetAttribute((const void*)lstm_rec<64,  2, false, false>,
                         cudaFuncAttributeMaxDynamicSharedMemorySize, SMEM2);

    // Layer 1
    proj_gemm<64, 512, true ><<<dim3(1024, 4), 256>>>(x,  W1, b1, zx1);
    lstm_rec<128, 2, true,  true ><<<128, 256, SMEM1>>>(zx1, Uw1, h1);
    // Layer 2
    proj_gemm<128, 256, false><<<dim3(1024, 2), 256>>>(h1, W2, b2, zx2);
    lstm_rec<64,  2, false, true ><<<128, 256, SMEM2>>>(zx2, Uw2, h2);
    // Layer 3 (only last hidden step needed)
    proj_gemm<64, 256, false><<<dim3(1024, 2), 256>>>(h2, W3, b3, zx3);
    lstm_rec<64,  2, false, false><<<128, 256, SMEM2>>>(zx3, Uw3, h3);
    // Dense head
    dense_kernel<<<1, 256>>>(h3, Wd1, bd1, Wd2, bd2, (float*)d_out);
}

// round 3
// speedup vs baseline: 1.4304x; 1.4304x over previous
#include <cuda_runtime.h>
#include <cuda_fp16.h>

// Problem constants
#define BB 256    // batch
#define TT 512    // timesteps

typedef unsigned long long ull;

// ---------------------------------------------------------------------------
// f32x2 packed-math helpers (Blackwell 2xFP32 pipe)
// ---------------------------------------------------------------------------
__device__ __forceinline__ void ffma2(ull& d, ull a, ull b) {
    asm("fma.rn.f32x2 %0, %1, %2, %0;" : "+l"(d) : "l"(a), "l"(b));
}
__device__ __forceinline__ ull pack2(float x, float y) {
    ull r; asm("mov.b64 %0, {%1, %2};" : "=l"(r) : "f"(x), "f"(y)); return r;
}
__device__ __forceinline__ float2 unpk2(ull v) {
    float2 f; asm("mov.b64 {%0, %1}, %2;" : "=f"(f.x), "=f"(f.y) : "l"(v)); return f;
}
__device__ __forceinline__ ull addx2(ull a, ull b) {
    ull r; asm("add.rn.f32x2 %0, %1, %2;" : "=l"(r) : "l"(a), "l"(b)); return r;
}
__device__ __forceinline__ float sigf(float x) {
    return 1.0f / (1.0f + __expf(-x));
}

// ---------------------------------------------------------------------------
// Device scratch (no cudaMalloc allowed)
// ---------------------------------------------------------------------------
__device__ float g_zx1[TT * BB * 512];   // [T,B,4*128]
__device__ float g_h1 [TT * BB * 128];   // [T,B,128]
__device__ float g_zx2[TT * BB * 256];   // [T,B,4*64]
__device__ float g_h2 [TT * BB * 64];    // [T,B,64]
__device__ float g_zx3[TT * BB * 256];   // [T,B,4*64]
__device__ float g_h3 [BB * 64];         // last-step hidden of layer 3

// ---------------------------------------------------------------------------
// Projection GEMM with f32x2 inner product.
//   C[m][n] = A_row(m) . W[:,n] + bias[n],  m = t*B + b  (zx layout [T,B,4u])
// ---------------------------------------------------------------------------
template<int K, int N, bool GATHER>
__global__ __launch_bounds__(256) void proj_gemm(
    const float* __restrict__ A, const float* __restrict__ W,
    const float* __restrict__ bias, float* __restrict__ C)
{
    constexpr int BM = 128, BN = 128, BK = 8;
    __shared__ float As[BK][BM];
    __shared__ float Ws[BK][BN];

    const int tid = threadIdx.x;
    const int m0  = blockIdx.x * BM;
    const int n0  = blockIdx.y * BN;

    const int arow = tid >> 1;
    const int acol = (tid & 1) << 2;
    const int wk = tid >> 5;
    const int wn = (tid & 31) << 2;

    const float* a_src;
    {
        int mrow = m0 + arow;
        if (GATHER) {
            int b = mrow & (BB - 1);
            int t = mrow >> 8;
            a_src = A + ((long)b * TT + t) * K + acol;
        } else {
            a_src = A + (long)mrow * K + acol;
        }
    }
    const float* w_src = W + (long)wk * N + n0 + wn;

    const int tx = tid & 15;
    const int ty = tid >> 4;

    ull acc2[8][4];
#pragma unroll
    for (int i = 0; i < 8; i++)
#pragma unroll
        for (int j = 0; j < 4; j++) acc2[i][j] = 0ull;

    for (int kt = 0; kt < K; kt += BK) {
        float4 av = *reinterpret_cast<const float4*>(a_src + kt);
        float4 wv = *reinterpret_cast<const float4*>(w_src + (long)kt * N);
        As[acol + 0][arow] = av.x;
        As[acol + 1][arow] = av.y;
        As[acol + 2][arow] = av.z;
        As[acol + 3][arow] = av.w;
        *reinterpret_cast<float4*>(&Ws[wk][wn]) = wv;
        __syncthreads();

#pragma unroll
        for (int k = 0; k < BK; k++) {
            float4 a0 = *reinterpret_cast<const float4*>(&As[k][ty * 8]);
            float4 a1 = *reinterpret_cast<const float4*>(&As[k][ty * 8 + 4]);
            float4 b0 = *reinterpret_cast<const float4*>(&Ws[k][tx * 8]);
            float4 b1 = *reinterpret_cast<const float4*>(&Ws[k][tx * 8 + 4]);
            ull br[4] = { pack2(b0.x, b0.y), pack2(b0.z, b0.w),
                          pack2(b1.x, b1.y), pack2(b1.z, b1.w) };
            float ar[8] = {a0.x, a0.y, a0.z, a0.w, a1.x, a1.y, a1.z, a1.w};
#pragma unroll
            for (int i = 0; i < 8; i++) {
                ull ai = pack2(ar[i], ar[i]);
#pragma unroll
                for (int j = 0; j < 4; j++) ffma2(acc2[i][j], ai, br[j]);
            }
        }
        __syncthreads();
    }

    float bb[8];
#pragma unroll
    for (int j = 0; j < 8; j++) bb[j] = bias[n0 + tx * 8 + j];

#pragma unroll
    for (int i = 0; i < 8; i++) {
        long m = m0 + ty * 8 + i;
        float2 p0 = unpk2(acc2[i][0]);
        float2 p1 = unpk2(acc2[i][1]);
        float2 p2 = unpk2(acc2[i][2]);
        float2 p3 = unpk2(acc2[i][3]);
        float4 o0, o1;
        o0.x = p0.x + bb[0]; o0.y = p0.y + bb[1];
        o0.z = p1.x + bb[2]; o0.w = p1.y + bb[3];
        o1.x = p2.x + bb[4]; o1.y = p2.y + bb[5];
        o1.z = p3.x + bb[6]; o1.w = p3.y + bb[7];
        *reinterpret_cast<float4*>(&C[m * N + n0 + tx * 8])     = o0;
        *reinterpret_cast<float4*>(&C[m * N + n0 + tx * 8 + 4]) = o1;
    }
}

// ---------------------------------------------------------------------------
// Layer-1 recurrence: U=128, G=512. 128 CTAs x 256 threads, 2 batch rows/CTA.
// Weights live in REGISTERS as half2 k-pairs: thread owns cols {tid, tid+256}.
// h stored in SMEM as fp16 (broadcast reads). HFMA2 partial sums flushed to
// fp32 every 16 k.
// Gate order [i,f,g,o]; c = sig(f)*c + sig(i)*relu(g); h = sig(o)*relu(c).
// ---------------------------------------------------------------------------
__global__ __launch_bounds__(256) void lstm1_rec(
    const float* __restrict__ zx,   // [T,B,512]
    const float* __restrict__ Uw,   // [128,512]
    float* __restrict__ h_out)      // [T,B,128]
{
    constexpr int U = 128, G = 512;
    __shared__ __half h_s[2][2][U];
    __shared__ float  z_s[2][G];

    const int tid = threadIdx.x;
    const int b0  = blockIdx.x * 2;
    const int c0  = tid;
    const int c1  = tid + 256;

    // Load weight slices into registers (k-pairs as half2)
    half2 w0[U / 2], w1[U / 2];
#pragma unroll
    for (int k2 = 0; k2 < U / 2; k2++) {
        w0[k2] = __floats2half2_rn(Uw[(2 * k2) * G + c0], Uw[(2 * k2 + 1) * G + c0]);
        w1[k2] = __floats2half2_rn(Uw[(2 * k2) * G + c1], Uw[(2 * k2 + 1) * G + c1]);
    }
    for (int i = tid; i < 2 * 2 * U; i += 256)
        (&h_s[0][0][0])[i] = __float2half_rn(0.f);
    __syncthreads();

    const int cu = tid & 127;   // combine role: unit
    const int cr = tid >> 7;    // combine role: row
    float creg = 0.f;

    // zx prefetch (t = 0)
    float zp00 = zx[(b0 + 0) * G + c0];
    float zp01 = zx[(b0 + 1) * G + c0];
    float zp10 = zx[(b0 + 0) * G + c1];
    float zp11 = zx[(b0 + 1) * G + c1];

    const half2 h2z = __floats2half2_rn(0.f, 0.f);
    int cur = 0;
#pragma unroll 1
    for (int t = 0; t < TT; t++) {
        float a00 = zp00, a01 = zp01, a10 = zp10, a11 = zp11;
        if (t + 1 < TT) {
            const float* zn = zx + ((long)(t + 1) * BB + b0) * G;
            zp00 = zn[c0]; zp01 = zn[G + c0];
            zp10 = zn[c1]; zp11 = zn[G + c1];
        }

#pragma unroll
        for (int kb = 0; kb < 8; kb++) {           // 16 k per block
            half2 s00 = h2z, s01 = h2z, s10 = h2z, s11 = h2z;
#pragma unroll
            for (int k8 = 0; k8 < 2; k8++) {       // 8 k per sub-block
                const int kbase = kb * 16 + k8 * 8;
                uint4 hv0 = *reinterpret_cast<const uint4*>(&h_s[cur][0][kbase]);
                uint4 hv1 = *reinterpret_cast<const uint4*>(&h_s[cur][1][kbase]);
                const half2* hp0 = reinterpret_cast<const half2*>(&hv0);
                const half2* hp1 = reinterpret_cast<const half2*>(&hv1);
#pragma unroll
                for (int j = 0; j < 4; j++) {
                    const int k2 = kbase / 2 + j;
                    s00 = __hfma2(w0[k2], hp0[j], s00);
                    s01 = __hfma2(w0[k2], hp1[j], s01);
                    s10 = __hfma2(w1[k2], hp0[j], s10);
                    s11 = __hfma2(w1[k2], hp1[j], s11);
                }
            }
            float2 f;
            f = __half22float2(s00); a00 += f.x + f.y;
            f = __half22float2(s01); a01 += f.x + f.y;
            f = __half22float2(s10); a10 += f.x + f.y;
            f = __half22float2(s11); a11 += f.x + f.y;
        }

        z_s[0][c0] = a00; z_s[1][c0] = a01;
        z_s[0][c1] = a10; z_s[1][c1] = a11;
        __syncthreads();

        // combine: all 256 threads (unit cu, row cr)
        {
            float zi = z_s[cr][cu];
            float zf = z_s[cr][U + cu];
            float zg = z_s[cr][2 * U + cu];
            float zo = z_s[cr][3 * U + cu];
            float ig = sigf(zi);
            float fg = sigf(zf);
            float gg = fmaxf(zg, 0.f);
            float og = sigf(zo);
            creg = fg * creg + ig * gg;
            float h = og * fmaxf(creg, 0.f);
            h_s[cur ^ 1][cr][cu] = __float2half_rn(h);
            h_out[((long)t * BB + b0 + cr) * U + cu] = h;
        }
        __syncthreads();
        cur ^= 1;
    }
}

// ---------------------------------------------------------------------------
// Layer-2/3 recurrence: U=64, G=256. 128 CTAs x 256 threads, 2 rows/CTA.
// Weights in REGISTERS as fp32 k-pairs (32 x b64 per thread), f32x2 FMA.
// ---------------------------------------------------------------------------
template<bool WRITE_ALL>
__global__ __launch_bounds__(256) void lstm64_rec(
    const float* __restrict__ zx,   // [T,B,256]
    const float* __restrict__ Uw,   // [64,256]
    float* __restrict__ h_out)      // [T,B,64] or [B,64]
{
    constexpr int U = 64, G = 256;
    __shared__ float h_s[2][2][U];
    __shared__ float z_s[2][G];

    const int tid = threadIdx.x;
    const int b0  = blockIdx.x * 2;

    ull wr[32];
#pragma unroll
    for (int k2 = 0; k2 < 32; k2++)
        wr[k2] = pack2(Uw[(2 * k2) * G + tid], Uw[(2 * k2 + 1) * G + tid]);
    for (int i = tid; i < 2 * 2 * U; i += 256)
        (&h_s[0][0][0])[i] = 0.f;
    __syncthreads();

    const int cu = tid & 63;
    const int cr = (tid >> 6) & 1;
    float creg = 0.f;

    float zp0 = zx[(b0 + 0) * G + tid];
    float zp1 = zx[(b0 + 1) * G + tid];

    int cur = 0;
#pragma unroll 1
    for (int t = 0; t < TT; t++) {
        float z0 = zp0, z1 = zp1;
        if (t + 1 < TT) {
            const float* zn = zx + ((long)(t + 1) * BB + b0) * G;
            zp0 = zn[tid]; zp1 = zn[G + tid];
        }

        ull a0a = 0ull, a0b = 0ull, a1a = 0ull, a1b = 0ull;
#pragma unroll
        for (int k4 = 0; k4 < 16; k4++) {
            float4 h0 = *reinterpret_cast<const float4*>(&h_s[cur][0][k4 * 4]);
            float4 h1 = *reinterpret_cast<const float4*>(&h_s[cur][1][k4 * 4]);
            ull h0a = pack2(h0.x, h0.y), h0b = pack2(h0.z, h0.w);
            ull h1a = pack2(h1.x, h1.y), h1b = pack2(h1.z, h1.w);
            ffma2(a0a, wr[2 * k4],     h0a);
            ffma2(a0b, wr[2 * k4 + 1], h0b);
            ffma2(a1a, wr[2 * k4],     h1a);
            ffma2(a1b, wr[2 * k4 + 1], h1b);
        }
        float2 f0 = unpk2(addx2(a0a, a0b));
        float2 f1 = unpk2(addx2(a1a, a1b));
        z_s[0][tid] = z0 + f0.x + f0.y;
        z_s[1][tid] = z1 + f1.x + f1.y;
        __syncthreads();

        if (tid < 2 * U) {
            float zi = z_s[cr][cu];
            float zf = z_s[cr][U + cu];
            float zg = z_s[cr][2 * U + cu];
            float zo = z_s[cr][3 * U + cu];
            float ig = sigf(zi);
            float fg = sigf(zf);
            float gg = fmaxf(zg, 0.f);
            float og = sigf(zo);
            creg = fg * creg + ig * gg;
            float h = og * fmaxf(creg, 0.f);
            h_s[cur ^ 1][cr][cu] = h;
            if (WRITE_ALL) {
                h_out[((long)t * BB + b0 + cr) * U + cu] = h;
            } else if (t == TT - 1) {
                h_out[(b0 + cr) * U + cu] = h;
            }
        }
        __syncthreads();
        cur ^= 1;
    }
}

// ---------------------------------------------------------------------------
// Dense head: out[b] = relu(h3[b] @ Wd1 + bd1) @ Wd2 + bd2
// ---------------------------------------------------------------------------
__global__ __launch_bounds__(256) void dense_kernel(
    const float* __restrict__ h3, const float* __restrict__ Wd1,
    const float* __restrict__ bd1, const float* __restrict__ Wd2,
    const float* __restrict__ bd2, float* __restrict__ out)
{
    __shared__ float w1[64 * 32];
    __shared__ float w2[32];
    __shared__ float b1s[32];
    const int tid = threadIdx.x;
    for (int i = tid; i < 64 * 32; i += 256) w1[i] = Wd1[i];
    if (tid < 32) { w2[tid] = Wd2[tid]; b1s[tid] = bd1[tid]; }
    __syncthreads();

    float hr[64];
#pragma unroll
    for (int k4 = 0; k4 < 16; k4++)
        *reinterpret_cast<float4*>(&hr[4 * k4]) =
            *reinterpret_cast<const float4*>(&h3[tid * 64 + 4 * k4]);

    float o = bd2[0];
#pragma unroll 4
    for (int j = 0; j < 32; j++) {
        float d = b1s[j];
#pragma unroll
        for (int k = 0; k < 64; k++) d += hr[k] * w1[k * 32 + j];
        o += fmaxf(d, 0.f) * w2[j];
    }
    out[tid] = o;
}

// ---------------------------------------------------------------------------
// Launcher
// ---------------------------------------------------------------------------
extern "C" void kernel_launch(void* const* d_in, const int* in_sizes, int n_in,
                              void* d_out, int out_size)
{
    const float* x   = (const float*)d_in[0];
    const float* W1  = (const float*)d_in[1];
    const float* Uw1 = (const float*)d_in[2];
    const float* b1  = (const float*)d_in[3];
    const float* W2  = (const float*)d_in[4];
    const float* Uw2 = (const float*)d_in[5];
    const float* b2  = (const float*)d_in[6];
    const float* W3  = (const float*)d_in[7];
    const float* Uw3 = (const float*)d_in[8];
    const float* b3  = (const float*)d_in[9];
    const float* Wd1 = (const float*)d_in[10];
    const float* bd1 = (const float*)d_in[11];
    const float* Wd2 = (const float*)d_in[12];
    const float* bd2 = (const float*)d_in[13];

    float *zx1, *h1, *zx2, *h2, *zx3, *h3;
    cudaGetSymbolAddress((void**)&zx1, g_zx1);
    cudaGetSymbolAddress((void**)&h1,  g_h1);
    cudaGetSymbolAddress((void**)&zx2, g_zx2);
    cudaGetSymbolAddress((void**)&h2,  g_h2);
    cudaGetSymbolAddress((void**)&zx3, g_zx3);
    cudaGetSymbolAddress((void**)&h3,  g_h3);

    // Layer 1
    proj_gemm<64, 512, true ><<<dim3(1024, 4), 256>>>(x,  W1, b1, zx1);
    lstm1_rec<<<128, 256>>>(zx1, Uw1, h1);
    // Layer 2
    proj_gemm<128, 256, false><<<dim3(1024, 2), 256>>>(h1, W2, b2, zx2);
    lstm64_rec<true ><<<128, 256>>>(zx2, Uw2, h2);
    // Layer 3 (only last hidden step needed)
    proj_gemm<64, 256, false><<<dim3(1024, 2), 256>>>(h2, W3, b3, zx3);
    lstm64_rec<false><<<128, 256>>>(zx3, Uw3, h3);
    // Dense head
    dense_kernel<<<1, 256>>>(h3, Wd1, bd1, Wd2, bd2, (float*)d_out);
}

// round 4
// speedup vs baseline: 1.4350x; 1.0033x over previous
#include <cuda_runtime.h>
#include <cuda_fp16.h>

#define BB 256    // batch
#define TT 512    // timesteps

typedef unsigned long long ull;

// ---------------------------------------------------------------------------
// f32x2 packed-math helpers
// ---------------------------------------------------------------------------
__device__ __forceinline__ void ffma2(ull& d, ull a, ull b) {
    asm("fma.rn.f32x2 %0, %1, %2, %0;" : "+l"(d) : "l"(a), "l"(b));
}
__device__ __forceinline__ ull pack2(float x, float y) {
    ull r; asm("mov.b64 %0, {%1, %2};" : "=l"(r) : "f"(x), "f"(y)); return r;
}
__device__ __forceinline__ float2 unpk2(ull v) {
    float2 f; asm("mov.b64 {%0, %1}, %2;" : "=f"(f.x), "=f"(f.y) : "l"(v)); return f;
}
__device__ __forceinline__ ull addx2(ull a, ull b) {
    ull r; asm("add.rn.f32x2 %0, %1, %2;" : "=l"(r) : "l"(a), "l"(b)); return r;
}
__device__ __forceinline__ float sigf(float x) {
    return __fdividef(1.0f, 1.0f + __expf(-x));
}

// Quad-gate select: value held = gate g; p1 = gate g^1; rv = gate g^2; p2 = gate g^3.
// Returns (zi, zf, zg, zo) = gates (0,1,2,3).
__device__ __forceinline__ void quad_select(
    int g, float zm, float p1, float rv, float p2,
    float& zi, float& zf, float& zg, float& zo)
{
    bool lo = g & 1, hi = g & 2;
    zi = hi ? (lo ? p2 : rv) : (lo ? p1 : zm);
    zf = hi ? (lo ? rv : p2) : (lo ? zm : p1);
    zg = hi ? (lo ? p1 : zm) : (lo ? p2 : rv);
    zo = hi ? (lo ? zm : p1) : (lo ? rv : p2);
}

// ---------------------------------------------------------------------------
// Device scratch
// ---------------------------------------------------------------------------
__device__ float g_zx1[TT * BB * 512];   // [T,B,4*128]
__device__ float g_h1 [TT * BB * 128];   // [T,B,128]
__device__ float g_zx2[TT * BB * 256];   // [T,B,4*64]
__device__ float g_h2 [TT * BB * 64];    // [T,B,64]
__device__ float g_zx3[TT * BB * 256];   // [T,B,4*64]
__device__ float g_h3 [BB * 64];         // last-step hidden of layer 3

// ---------------------------------------------------------------------------
// Projection GEMM (f32x2 inner product), unchanged from R3.
// ---------------------------------------------------------------------------
template<int K, int N, bool GATHER>
__global__ __launch_bounds__(256) void proj_gemm(
    const float* __restrict__ A, const float* __restrict__ W,
    const float* __restrict__ bias, float* __restrict__ C)
{
    constexpr int BM = 128, BN = 128, BK = 8;
    __shared__ float As[BK][BM];
    __shared__ float Ws[BK][BN];

    const int tid = threadIdx.x;
    const int m0  = blockIdx.x * BM;
    const int n0  = blockIdx.y * BN;

    const int arow = tid >> 1;
    const int acol = (tid & 1) << 2;
    const int wk = tid >> 5;
    const int wn = (tid & 31) << 2;

    const float* a_src;
    {
        int mrow = m0 + arow;
        if (GATHER) {
            int b = mrow & (BB - 1);
            int t = mrow >> 8;
            a_src = A + ((long)b * TT + t) * K + acol;
        } else {
            a_src = A + (long)mrow * K + acol;
        }
    }
    const float* w_src = W + (long)wk * N + n0 + wn;

    const int tx = tid & 15;
    const int ty = tid >> 4;

    ull acc2[8][4];
#pragma unroll
    for (int i = 0; i < 8; i++)
#pragma unroll
        for (int j = 0; j < 4; j++) acc2[i][j] = 0ull;

    for (int kt = 0; kt < K; kt += BK) {
        float4 av = *reinterpret_cast<const float4*>(a_src + kt);
        float4 wv = *reinterpret_cast<const float4*>(w_src + (long)kt * N);
        As[acol + 0][arow] = av.x;
        As[acol + 1][arow] = av.y;
        As[acol + 2][arow] = av.z;
        As[acol + 3][arow] = av.w;
        *reinterpret_cast<float4*>(&Ws[wk][wn]) = wv;
        __syncthreads();

#pragma unroll
        for (int k = 0; k < BK; k++) {
            float4 a0 = *reinterpret_cast<const float4*>(&As[k][ty * 8]);
            float4 a1 = *reinterpret_cast<const float4*>(&As[k][ty * 8 + 4]);
            ulonglong2 b0 = *reinterpret_cast<const ulonglong2*>(&Ws[k][tx * 8]);
            ulonglong2 b1 = *reinterpret_cast<const ulonglong2*>(&Ws[k][tx * 8 + 4]);
            ull br[4] = { b0.x, b0.y, b1.x, b1.y };
            float ar[8] = {a0.x, a0.y, a0.z, a0.w, a1.x, a1.y, a1.z, a1.w};
#pragma unroll
            for (int i = 0; i < 8; i++) {
                ull ai = pack2(ar[i], ar[i]);
#pragma unroll
                for (int j = 0; j < 4; j++) ffma2(acc2[i][j], ai, br[j]);
            }
        }
        __syncthreads();
    }

    float bb[8];
#pragma unroll
    for (int j = 0; j < 8; j++) bb[j] = bias[n0 + tx * 8 + j];

#pragma unroll
    for (int i = 0; i < 8; i++) {
        long m = m0 + ty * 8 + i;
        float2 p0 = unpk2(acc2[i][0]);
        float2 p1 = unpk2(acc2[i][1]);
        float2 p2 = unpk2(acc2[i][2]);
        float2 p3 = unpk2(acc2[i][3]);
        float4 o0, o1;
        o0.x = p0.x + bb[0]; o0.y = p0.y + bb[1];
        o0.z = p1.x + bb[2]; o0.w = p1.y + bb[3];
        o1.x = p2.x + bb[4]; o1.y = p2.y + bb[5];
        o1.z = p3.x + bb[6]; o1.w = p3.y + bb[7];
        *reinterpret_cast<float4*>(&C[m * N + n0 + tx * 8])     = o0;
        *reinterpret_cast<float4*>(&C[m * N + n0 + tx * 8 + 4]) = o1;
    }
}

// ---------------------------------------------------------------------------
// Layer-2/3 recurrence: U=64, G=256, 2 rows/CTA, 128 CTAs x 256 threads.
// One barrier per step; quad-shuffle gate combine; weights in registers.
// Thread -> (gate g = tid&3, unit j = tid>>2), col = g*64 + j.
// Lanes g in {0,1} combine row 0, g in {2,3} combine row 1.
// ---------------------------------------------------------------------------
template<bool WRITE_ALL>
__global__ __launch_bounds__(256) void lstm64_rec(
    const float* __restrict__ zx,   // [T,B,256]
    const float* __restrict__ Uw,   // [64,256]
    float* __restrict__ h_out)      // [T,B,64] or [B,64]
{
    constexpr int U = 64, G = 256;
    __shared__ float h_s[2][2][U];  // [buf][row][unit]

    const int tid = threadIdx.x;
    const int b0  = blockIdx.x * 2;
    const int g   = tid & 3;
    const int j   = tid >> 2;
    const int col = g * U + j;
    const int myrow = (g >> 1) & 1;

    ull wr[32];
#pragma unroll
    for (int k2 = 0; k2 < 32; k2++)
        wr[k2] = pack2(Uw[(2 * k2) * G + col], Uw[(2 * k2 + 1) * G + col]);
    (&h_s[0][0][0])[tid] = 0.f;     // zero both buffers (256 floats)
    __syncthreads();

    float creg = 0.f;
    float zp0 = zx[(b0 + 0) * G + col];
    float zp1 = zx[(b0 + 1) * G + col];

    int cur = 0;
#pragma unroll 1
    for (int t = 0; t < TT; t++) {
        ull a0a = 0ull, a0b = 0ull, a1a = 0ull, a1b = 0ull;
        const ulonglong2* h0p = reinterpret_cast<const ulonglong2*>(&h_s[cur][0][0]);
        const ulonglong2* h1p = reinterpret_cast<const ulonglong2*>(&h_s[cur][1][0]);
#pragma unroll
        for (int k4 = 0; k4 < 16; k4++) {
            ulonglong2 h0 = h0p[k4];
            ulonglong2 h1 = h1p[k4];
            ffma2(a0a, wr[2 * k4],     h0.x);
            ffma2(a0b, wr[2 * k4 + 1], h0.y);
            ffma2(a1a, wr[2 * k4],     h1.x);
            ffma2(a1b, wr[2 * k4 + 1], h1.y);
        }
        float2 f0 = unpk2(addx2(a0a, a0b));
        float2 f1 = unpk2(addx2(a1a, a1b));
        float z0 = zp0 + f0.x + f0.y;
        float z1 = zp1 + f1.x + f1.y;

        if (t + 1 < TT) {
            const float* zn = zx + ((long)(t + 1) * BB + b0) * G;
            zp0 = zn[col]; zp1 = zn[G + col];
        }

        // quad shuffle: get all 4 gates of my row into this lane
        float zm = myrow ? z1 : z0;
        float zo_ = myrow ? z0 : z1;
        float rv = __shfl_xor_sync(0xffffffffu, zo_, 2);   // gate g^2, my row
        float p1 = __shfl_xor_sync(0xffffffffu, zm, 1);    // gate g^1
        float p2 = __shfl_xor_sync(0xffffffffu, rv, 1);    // gate g^3

        float zi, zf, zg_, zoo;
        quad_select(g, zm, p1, rv, p2, zi, zf, zg_, zoo);

        float ig = sigf(zi);
        float fg = sigf(zf);
        float gg = fmaxf(zg_, 0.f);
        float og = sigf(zoo);
        creg = fg * creg + ig * gg;
        float h = og * fmaxf(creg, 0.f);

        if ((g & 1) == 0) {
            h_s[cur ^ 1][myrow][j] = h;
            if (WRITE_ALL)
                h_out[((long)t * BB + b0 + myrow) * U + j] = h;
            else if (t == TT - 1)
                h_out[(b0 + myrow) * U + j] = h;
        }
        __syncthreads();
        cur ^= 1;
    }
}

// ---------------------------------------------------------------------------
// Layer-1 recurrence: U=128, G=512, 2 rows/CTA, 128 CTAs x 256 threads.
// Thread owns 2 columns (units j and j+64, gate g). Weights fp16 in regs,
// HFMA2 partial sums flushed to fp32 every 32 k. One barrier per step.
// ---------------------------------------------------------------------------
__global__ __launch_bounds__(256) void lstm1_rec(
    const float* __restrict__ zx,   // [T,B,512]
    const float* __restrict__ Uw,   // [128,512]
    float* __restrict__ h_out)      // [T,B,128]
{
    constexpr int U = 128, G = 512;
    __shared__ __half h_s[2][2][U];

    const int tid = threadIdx.x;
    const int b0  = blockIdx.x * 2;
    const int g   = tid & 3;
    const int j0  = tid >> 2;           // units j0 and j0+64
    const int c0  = g * U + j0;
    const int c1  = g * U + j0 + 64;
    const int myrow = (g >> 1) & 1;

    half2 w0[U / 2], w1[U / 2];
#pragma unroll
    for (int k2 = 0; k2 < U / 2; k2++) {
        w0[k2] = __floats2half2_rn(Uw[(2 * k2) * G + c0], Uw[(2 * k2 + 1) * G + c0]);
        w1[k2] = __floats2half2_rn(Uw[(2 * k2) * G + c1], Uw[(2 * k2 + 1) * G + c1]);
    }
    for (int i = tid; i < 2 * 2 * U; i += 256)
        (&h_s[0][0][0])[i] = __float2half_rn(0.f);
    __syncthreads();

    float c_a = 0.f, c_b = 0.f;   // cell state for units j0, j0+64 (my row)
    float zp00 = zx[(b0 + 0) * G + c0];
    float zp01 = zx[(b0 + 1) * G + c0];
    float zp10 = zx[(b0 + 0) * G + c1];
    float zp11 = zx[(b0 + 1) * G + c1];

    const half2 h2z = __floats2half2_rn(0.f, 0.f);
    int cur = 0;
#pragma unroll 1
    for (int t = 0; t < TT; t++) {
        float a00 = zp00, a01 = zp01, a10 = zp10, a11 = zp11;
        if (t + 1 < TT) {
            const float* zn = zx + ((long)(t + 1) * BB + b0) * G;
            zp00 = zn[c0]; zp01 = zn[G + c0];
            zp10 = zn[c1]; zp11 = zn[G + c1];
        }

#pragma unroll
        for (int kb = 0; kb < 4; kb++) {            // 32 k per block
            half2 s00 = h2z, s01 = h2z, s10 = h2z, s11 = h2z;
#pragma unroll
            for (int k8 = 0; k8 < 4; k8++) {        // 8 k per sub-block
                const int kbase = kb * 32 + k8 * 8;
                uint4 hv0 = *reinterpret_cast<const uint4*>(&h_s[cur][0][kbase]);
                uint4 hv1 = *reinterpret_cast<const uint4*>(&h_s[cur][1][kbase]);
                const half2* hp0 = reinterpret_cast<const half2*>(&hv0);
                const half2* hp1 = reinterpret_cast<const half2*>(&hv1);
#pragma unroll
                for (int q = 0; q < 4; q++) {
                    const int k2 = kbase / 2 + q;
                    s00 = __hfma2(w0[k2], hp0[q], s00);
                    s01 = __hfma2(w0[k2], hp1[q], s01);
                    s10 = __hfma2(w1[k2], hp0[q], s10);
                    s11 = __hfma2(w1[k2], hp1[q], s11);
                }
            }
            float2 f;
            f = __half22float2(s00); a00 += f.x + f.y;
            f = __half22float2(s01); a01 += f.x + f.y;
            f = __half22float2(s10); a10 += f.x + f.y;
            f = __half22float2(s11); a11 += f.x + f.y;
        }

        // quad shuffles for both units (my row only)
        float zmA = myrow ? a01 : a00;
        float zoA = myrow ? a00 : a01;
        float zmB = myrow ? a11 : a10;
        float zoB = myrow ? a10 : a11;
        float rvA = __shfl_xor_sync(0xffffffffu, zoA, 2);
        float rvB = __shfl_xor_sync(0xffffffffu, zoB, 2);
        float p1A = __shfl_xor_sync(0xffffffffu, zmA, 1);
        float p1B = __shfl_xor_sync(0xffffffffu, zmB, 1);
        float p2A = __shfl_xor_sync(0xffffffffu, rvA, 1);
        float p2B = __shfl_xor_sync(0xffffffffu, rvB, 1);

        float zi, zf, zg_, zoo;
        quad_select(g, zmA, p1A, rvA, p2A, zi, zf, zg_, zoo);
        float ig = sigf(zi), fg = sigf(zf), og = sigf(zoo);
        c_a = fg * c_a + ig * fmaxf(zg_, 0.f);
        float hA = og * fmaxf(c_a, 0.f);

        quad_select(g, zmB, p1B, rvB, p2B, zi, zf, zg_, zoo);
        ig = sigf(zi); fg = sigf(zf); og = sigf(zoo);
        c_b = fg * c_b + ig * fmaxf(zg_, 0.f);
        float hB = og * fmaxf(c_b, 0.f);

        if ((g & 1) == 0) {
            h_s[cur ^ 1][myrow][j0]      = __float2half_rn(hA);
            h_s[cur ^ 1][myrow][j0 + 64] = __float2half_rn(hB);
            float* ho = h_out + ((long)t * BB + b0 + myrow) * U;
            ho[j0]      = hA;
            ho[j0 + 64] = hB;
        }
        __syncthreads();
        cur ^= 1;
    }
}

// ---------------------------------------------------------------------------
// Dense head
// ---------------------------------------------------------------------------
__global__ __launch_bounds__(256) void dense_kernel(
    const float* __restrict__ h3, const float* __restrict__ Wd1,
    const float* __restrict__ bd1, const float* __restrict__ Wd2,
    const float* __restrict__ bd2, float* __restrict__ out)
{
    __shared__ float w1[64 * 32];
    __shared__ float w2[32];
    __shared__ float b1s[32];
    const int tid = threadIdx.x;
    for (int i = tid; i < 64 * 32; i += 256) w1[i] = Wd1[i];
    if (tid < 32) { w2[tid] = Wd2[tid]; b1s[tid] = bd1[tid]; }
    __syncthreads();

    float hr[64];
#pragma unroll
    for (int k4 = 0; k4 < 16; k4++)
        *reinterpret_cast<float4*>(&hr[4 * k4]) =
            *reinterpret_cast<const float4*>(&h3[tid * 64 + 4 * k4]);

    float o = bd2[0];
#pragma unroll 4
    for (int jj = 0; jj < 32; jj++) {
        float d = b1s[jj];
#pragma unroll
        for (int k = 0; k < 64; k++) d += hr[k] * w1[k * 32 + jj];
        o += fmaxf(d, 0.f) * w2[jj];
    }
    out[tid] = o;
}

// ---------------------------------------------------------------------------
// Launcher
// ---------------------------------------------------------------------------
extern "C" void kernel_launch(void* const* d_in, const int* in_sizes, int n_in,
                              void* d_out, int out_size)
{
    const float* x   = (const float*)d_in[0];
    const float* W1  = (const float*)d_in[1];
    const float* Uw1 = (const float*)d_in[2];
    const float* b1  = (const float*)d_in[3];
    const float* W2  = (const float*)d_in[4];
    const float* Uw2 = (const float*)d_in[5];
    const float* b2  = (const float*)d_in[6];
    const float* W3  = (const float*)d_in[7];
    const float* Uw3 = (const float*)d_in[8];
    const float* b3  = (const float*)d_in[9];
    const float* Wd1 = (const float*)d_in[10];
    const float* bd1 = (const float*)d_in[11];
    const float* Wd2 = (const float*)d_in[12];
    const float* bd2 = (const float*)d_in[13];

    float *zx1, *h1, *zx2, *h2, *zx3, *h3;
    cudaGetSymbolAddress((void**)&zx1, g_zx1);
    cudaGetSymbolAddress((void**)&h1,  g_h1);
    cudaGetSymbolAddress((void**)&zx2, g_zx2);
    cudaGetSymbolAddress((void**)&h2,  g_h2);
    cudaGetSymbolAddress((void**)&zx3, g_zx3);
    cudaGetSymbolAddress((void**)&h3,  g_h3);

    // Layer 1
    proj_gemm<64, 512, true ><<<dim3(1024, 4), 256>>>(x,  W1, b1, zx1);
    lstm1_rec<<<128, 256>>>(zx1, Uw1, h1);
    // Layer 2
    proj_gemm<128, 256, false><<<dim3(1024, 2), 256>>>(h1, W2, b2, zx2);
    lstm64_rec<true ><<<128, 256>>>(zx2, Uw2, h2);
    // Layer 3 (only last hidden step needed)
    proj_gemm<64, 256, false><<<dim3(1024, 2), 256>>>(h2, W3, b3, zx3);
    lstm64_rec<false><<<128, 256>>>(zx3, Uw3, h3);
    // Dense head
    dense_kernel<<<1, 256>>>(h3, Wd1, bd1, Wd2, bd2, (float*)d_out);
}

// round 5
// speedup vs baseline: 1.6080x; 1.1205x over previous
#include <cuda_runtime.h>
#include <cuda_fp16.h>

#define BB 256    // batch
#define TT 512    // timesteps

typedef unsigned long long ull;

// ---------------------------------------------------------------------------
// f32x2 packed-math helpers
// ---------------------------------------------------------------------------
__device__ __forceinline__ void ffma2(ull& d, ull a, ull b) {
    asm("fma.rn.f32x2 %0, %1, %2, %0;" : "+l"(d) : "l"(a), "l"(b));
}
__device__ __forceinline__ ull pack2(float x, float y) {
    ull r; asm("mov.b64 %0, {%1, %2};" : "=l"(r) : "f"(x), "f"(y)); return r;
}
__device__ __forceinline__ float2 unpk2(ull v) {
    float2 f; asm("mov.b64 {%0, %1}, %2;" : "=f"(f.x), "=f"(f.y) : "l"(v)); return f;
}
__device__ __forceinline__ ull addx2(ull a, ull b) {
    ull r; asm("add.rn.f32x2 %0, %1, %2;" : "=l"(r) : "l"(a), "l"(b)); return r;
}
__device__ __forceinline__ float sigf(float x) {
    return __fdividef(1.0f, 1.0f + __expf(-x));
}

// Quad-gate select: mine = gate g; p1 = gate g^1; rv = gate g^2; p2 = gate g^3.
__device__ __forceinline__ void quad_select(
    int g, float zm, float p1, float rv, float p2,
    float& zi, float& zf, float& zg, float& zo)
{
    bool lo = g & 1, hi = g & 2;
    zi = hi ? (lo ? p2 : rv) : (lo ? p1 : zm);
    zf = hi ? (lo ? rv : p2) : (lo ? zm : p1);
    zg = hi ? (lo ? p1 : zm) : (lo ? p2 : rv);
    zo = hi ? (lo ? zm : p1) : (lo ? rv : p2);
}

// ---------------------------------------------------------------------------
// Device scratch
// ---------------------------------------------------------------------------
__device__ float g_zx1[TT * BB * 512];   // [T,B,4*128]
__device__ float g_h1 [TT * BB * 128];   // [T,B,128]
__device__ float g_zx2[TT * BB * 256];   // [T,B,4*64]
__device__ float g_h2 [TT * BB * 64];    // [T,B,64]
__device__ float g_zx3[TT * BB * 256];   // [T,B,4*64]
__device__ float g_h3 [BB * 64];         // last-step hidden of layer 3

// ---------------------------------------------------------------------------
// Projection GEMM (f32x2 inner product).
// ---------------------------------------------------------------------------
template<int K, int N, bool GATHER>
__global__ __launch_bounds__(256) void proj_gemm(
    const float* __restrict__ A, const float* __restrict__ W,
    const float* __restrict__ bias, float* __restrict__ C)
{
    constexpr int BM = 128, BN = 128, BK = 8;
    __shared__ float As[BK][BM];
    __shared__ float Ws[BK][BN];

    const int tid = threadIdx.x;
    const int m0  = blockIdx.x * BM;
    const int n0  = blockIdx.y * BN;

    const int arow = tid >> 1;
    const int acol = (tid & 1) << 2;
    const int wk = tid >> 5;
    const int wn = (tid & 31) << 2;

    const float* a_src;
    {
        int mrow = m0 + arow;
        if (GATHER) {
            int b = mrow & (BB - 1);
            int t = mrow >> 8;
            a_src = A + ((long)b * TT + t) * K + acol;
        } else {
            a_src = A + (long)mrow * K + acol;
        }
    }
    const float* w_src = W + (long)wk * N + n0 + wn;

    const int tx = tid & 15;
    const int ty = tid >> 4;

    ull acc2[8][4];
#pragma unroll
    for (int i = 0; i < 8; i++)
#pragma unroll
        for (int j = 0; j < 4; j++) acc2[i][j] = 0ull;

    for (int kt = 0; kt < K; kt += BK) {
        float4 av = *reinterpret_cast<const float4*>(a_src + kt);
        float4 wv = *reinterpret_cast<const float4*>(w_src + (long)kt * N);
        As[acol + 0][arow] = av.x;
        As[acol + 1][arow] = av.y;
        As[acol + 2][arow] = av.z;
        As[acol + 3][arow] = av.w;
        *reinterpret_cast<float4*>(&Ws[wk][wn]) = wv;
        __syncthreads();

#pragma unroll
        for (int k = 0; k < BK; k++) {
            float4 a0 = *reinterpret_cast<const float4*>(&As[k][ty * 8]);
            float4 a1 = *reinterpret_cast<const float4*>(&As[k][ty * 8 + 4]);
            ulonglong2 b0 = *reinterpret_cast<const ulonglong2*>(&Ws[k][tx * 8]);
            ulonglong2 b1 = *reinterpret_cast<const ulonglong2*>(&Ws[k][tx * 8 + 4]);
            ull br[4] = { b0.x, b0.y, b1.x, b1.y };
            float ar[8] = {a0.x, a0.y, a0.z, a0.w, a1.x, a1.y, a1.z, a1.w};
#pragma unroll
            for (int i = 0; i < 8; i++) {
                ull ai = pack2(ar[i], ar[i]);
#pragma unroll
                for (int j = 0; j < 4; j++) ffma2(acc2[i][j], ai, br[j]);
            }
        }
        __syncthreads();
    }

    float bb[8];
#pragma unroll
    for (int j = 0; j < 8; j++) bb[j] = bias[n0 + tx * 8 + j];

#pragma unroll
    for (int i = 0; i < 8; i++) {
        long m = m0 + ty * 8 + i;
        float2 p0 = unpk2(acc2[i][0]);
        float2 p1 = unpk2(acc2[i][1]);
        float2 p2 = unpk2(acc2[i][2]);
        float2 p3 = unpk2(acc2[i][3]);
        float4 o0, o1;
        o0.x = p0.x + bb[0]; o0.y = p0.y + bb[1];
        o0.z = p1.x + bb[2]; o0.w = p1.y + bb[3];
        o1.x = p2.x + bb[4]; o1.y = p2.y + bb[5];
        o1.z = p3.x + bb[6]; o1.w = p3.y + bb[7];
        *reinterpret_cast<float4*>(&C[m * N + n0 + tx * 8])     = o0;
        *reinterpret_cast<float4*>(&C[m * N + n0 + tx * 8 + 4]) = o1;
    }
}

// ---------------------------------------------------------------------------
// Layer-2/3 recurrence: U=64, G=256, 2 rows/CTA, 128 CTAs x 256 threads.
// Deep zx prefetch (4 steps), one barrier/step, independent 3-shuffle combine.
// Thread -> (gate g = tid&3, unit j = tid>>2), col = g*64 + j.
// ---------------------------------------------------------------------------
template<bool WRITE_ALL>
__global__ __launch_bounds__(256) void lstm64_rec(
    const float* __restrict__ zx,   // [T,B,256]
    const float* __restrict__ Uw,   // [64,256]
    float* __restrict__ h_out)      // [T,B,64] or [B,64]
{
    constexpr int U = 64, G = 256;
    constexpr int PF = 4;
    constexpr long ZSTRIDE = (long)BB * G;
    __shared__ float h_s[2][2][U];  // [buf][row][unit]

    const int tid = threadIdx.x;
    const int b0  = blockIdx.x * 2;
    const int g   = tid & 3;
    const int j   = tid >> 2;
    const int col = g * U + j;
    const int myrow = (g >> 1) & 1;

    ull wr[32];
#pragma unroll
    for (int k2 = 0; k2 < 32; k2++)
        wr[k2] = pack2(Uw[(2 * k2) * G + col], Uw[(2 * k2 + 1) * G + col]);
    (&h_s[0][0][0])[tid] = 0.f;
    __syncthreads();

    const float* zb0 = zx + (long)b0 * G + col;        // row b0
    const float* zb1 = zb0 + G;                        // row b0+1

    float creg = 0.f;
    float zA[PF], zB[PF];
#pragma unroll
    for (int p = 0; p < PF; p++) {
        zA[p] = zb0[(long)p * ZSTRIDE];
        zB[p] = zb1[(long)p * ZSTRIDE];
    }

    int cur = 0;
#pragma unroll 4
    for (int t = 0; t < TT; t++) {
        const int s = t & (PF - 1);
        float z0 = zA[s], z1 = zB[s];
        if (t + PF < TT) {
            zA[s] = zb0[(long)(t + PF) * ZSTRIDE];
            zB[s] = zb1[(long)(t + PF) * ZSTRIDE];
        }

        ull a0a = 0ull, a0b = 0ull, a1a = 0ull, a1b = 0ull;
        const ulonglong2* h0p = reinterpret_cast<const ulonglong2*>(&h_s[cur][0][0]);
        const ulonglong2* h1p = reinterpret_cast<const ulonglong2*>(&h_s[cur][1][0]);
#pragma unroll
        for (int k4 = 0; k4 < 16; k4++) {
            ulonglong2 h0 = h0p[k4];
            ulonglong2 h1 = h1p[k4];
            ffma2(a0a, wr[2 * k4],     h0.x);
            ffma2(a0b, wr[2 * k4 + 1], h0.y);
            ffma2(a1a, wr[2 * k4],     h1.x);
            ffma2(a1b, wr[2 * k4 + 1], h1.y);
        }
        float2 f0 = unpk2(addx2(a0a, a0b));
        float2 f1 = unpk2(addx2(a1a, a1b));
        z0 += f0.x + f0.y;
        z1 += f1.x + f1.y;

        // independent butterfly: gather all 4 gates of my row
        float mine  = myrow ? z1 : z0;
        float other = myrow ? z0 : z1;
        float p1 = __shfl_xor_sync(0xffffffffu, mine,  1);   // gate g^1
        float rv = __shfl_xor_sync(0xffffffffu, other, 2);   // gate g^2
        float p2 = __shfl_xor_sync(0xffffffffu, other, 3);   // gate g^3

        float zi, zf, zg_, zoo;
        quad_select(g, mine, p1, rv, p2, zi, zf, zg_, zoo);

        float ig = sigf(zi);
        float fg = sigf(zf);
        float gg = fmaxf(zg_, 0.f);
        float og = sigf(zoo);
        creg = fg * creg + ig * gg;
        float h = og * fmaxf(creg, 0.f);

        if ((g & 1) == 0) {
            h_s[cur ^ 1][myrow][j] = h;
            if (WRITE_ALL)
                h_out[((long)t * BB + b0 + myrow) * U + j] = h;
            else if (t == TT - 1)
                h_out[(b0 + myrow) * U + j] = h;
        }
        __syncthreads();
        cur ^= 1;
    }
}

// ---------------------------------------------------------------------------
// Layer-1 recurrence: U=128, G=512, 2 rows/CTA, 128 CTAs x 256 threads.
// Thread owns 2 columns (units j, j+64; gate g). fp16 weights in registers,
// HFMA2 flushed to fp32 every 32 k. Deep prefetch + butterfly combine.
// ---------------------------------------------------------------------------
__global__ __launch_bounds__(256) void lstm1_rec(
    const float* __restrict__ zx,   // [T,B,512]
    const float* __restrict__ Uw,   // [128,512]
    float* __restrict__ h_out)      // [T,B,128]
{
    constexpr int U = 128, G = 512;
    constexpr int PF = 4;
    constexpr long ZSTRIDE = (long)BB * G;
    __shared__ __half h_s[2][2][U];

    const int tid = threadIdx.x;
    const int b0  = blockIdx.x * 2;
    const int g   = tid & 3;
    const int j0  = tid >> 2;           // units j0 and j0+64
    const int c0  = g * U + j0;
    const int c1  = g * U + j0 + 64;
    const int myrow = (g >> 1) & 1;

    half2 w0[U / 2], w1[U / 2];
#pragma unroll
    for (int k2 = 0; k2 < U / 2; k2++) {
        w0[k2] = __floats2half2_rn(Uw[(2 * k2) * G + c0], Uw[(2 * k2 + 1) * G + c0]);
        w1[k2] = __floats2half2_rn(Uw[(2 * k2) * G + c1], Uw[(2 * k2 + 1) * G + c1]);
    }
    for (int i = tid; i < 2 * 2 * U; i += 256)
        (&h_s[0][0][0])[i] = __float2half_rn(0.f);
    __syncthreads();

    const float* z00p = zx + (long)b0 * G + c0;
    const float* z01p = z00p + G;
    const float* z10p = zx + (long)b0 * G + c1;
    const float* z11p = z10p + G;

    float c_a = 0.f, c_b = 0.f;
    float zA0[PF], zA1[PF], zB0[PF], zB1[PF];
#pragma unroll
    for (int p = 0; p < PF; p++) {
        zA0[p] = z00p[(long)p * ZSTRIDE];
        zA1[p] = z01p[(long)p * ZSTRIDE];
        zB0[p] = z10p[(long)p * ZSTRIDE];
        zB1[p] = z11p[(long)p * ZSTRIDE];
    }

    const half2 h2z = __floats2half2_rn(0.f, 0.f);
    int cur = 0;
#pragma unroll 4
    for (int t = 0; t < TT; t++) {
        const int s = t & (PF - 1);
        float a00 = zA0[s], a01 = zA1[s], a10 = zB0[s], a11 = zB1[s];
        if (t + PF < TT) {
            zA0[s] = z00p[(long)(t + PF) * ZSTRIDE];
            zA1[s] = z01p[(long)(t + PF) * ZSTRIDE];
            zB0[s] = z10p[(long)(t + PF) * ZSTRIDE];
            zB1[s] = z11p[(long)(t + PF) * ZSTRIDE];
        }

#pragma unroll
        for (int kb = 0; kb < 4; kb++) {            // 32 k per block
            half2 s00 = h2z, s01 = h2z, s10 = h2z, s11 = h2z;
#pragma unroll
            for (int k8 = 0; k8 < 4; k8++) {        // 8 k per sub-block
                const int kbase = kb * 32 + k8 * 8;
                uint4 hv0 = *reinterpret_cast<const uint4*>(&h_s[cur][0][kbase]);
                uint4 hv1 = *reinterpret_cast<const uint4*>(&h_s[cur][1][kbase]);
                const half2* hp0 = reinterpret_cast<const half2*>(&hv0);
                const half2* hp1 = reinterpret_cast<const half2*>(&hv1);
#pragma unroll
                for (int q = 0; q < 4; q++) {
                    const int k2 = kbase / 2 + q;
                    s00 = __hfma2(w0[k2], hp0[q], s00);
                    s01 = __hfma2(w0[k2], hp1[q], s01);
                    s10 = __hfma2(w1[k2], hp0[q], s10);
                    s11 = __hfma2(w1[k2], hp1[q], s11);
                }
            }
            float2 f;
            f = __half22float2(s00); a00 += f.x + f.y;
            f = __half22float2(s01); a01 += f.x + f.y;
            f = __half22float2(s10); a10 += f.x + f.y;
            f = __half22float2(s11); a11 += f.x + f.y;
        }

        // butterfly for unit set A
        float mineA  = myrow ? a01 : a00;
        float otherA = myrow ? a00 : a01;
        float mineB  = myrow ? a11 : a10;
        float otherB = myrow ? a10 : a11;
        float p1A = __shfl_xor_sync(0xffffffffu, mineA,  1);
        float rvA = __shfl_xor_sync(0xffffffffu, otherA, 2);
        float p2A = __shfl_xor_sync(0xffffffffu, otherA, 3);
        float p1B = __shfl_xor_sync(0xffffffffu, mineB,  1);
        float rvB = __shfl_xor_sync(0xffffffffu, otherB, 2);
        float p2B = __shfl_xor_sync(0xffffffffu, otherB, 3);

        float zi, zf, zg_, zoo;
        quad_select(g, mineA, p1A, rvA, p2A, zi, zf, zg_, zoo);
        float ig = sigf(zi), fg = sigf(zf), og = sigf(zoo);
        c_a = fg * c_a + ig * fmaxf(zg_, 0.f);
        float hA = og * fmaxf(c_a, 0.f);

        quad_select(g, mineB, p1B, rvB, p2B, zi, zf, zg_, zoo);
        ig = sigf(zi); fg = sigf(zf); og = sigf(zoo);
        c_b = fg * c_b + ig * fmaxf(zg_, 0.f);
        float hB = og * fmaxf(c_b, 0.f);

        if ((g & 1) == 0) {
            h_s[cur ^ 1][myrow][j0]      = __float2half_rn(hA);
            h_s[cur ^ 1][myrow][j0 + 64] = __float2half_rn(hB);
            float* ho = h_out + ((long)t * BB + b0 + myrow) * U;
            ho[j0]      = hA;
            ho[j0 + 64] = hB;
        }
        __syncthreads();
        cur ^= 1;
    }
}

// ---------------------------------------------------------------------------
// Dense head
// ---------------------------------------------------------------------------
__global__ __launch_bounds__(256) void dense_kernel(
    const float* __restrict__ h3, const float* __restrict__ Wd1,
    const float* __restrict__ bd1, const float* __restrict__ Wd2,
    const float* __restrict__ bd2, float* __restrict__ out)
{
    __shared__ float w1[64 * 32];
    __shared__ float w2[32];
    __shared__ float b1s[32];
    const int tid = threadIdx.x;
    for (int i = tid; i < 64 * 32; i += 256) w1[i] = Wd1[i];
    if (tid < 32) { w2[tid] = Wd2[tid]; b1s[tid] = bd1[tid]; }
    __syncthreads();

    float hr[64];
#pragma unroll
    for (int k4 = 0; k4 < 16; k4++)
        *reinterpret_cast<float4*>(&hr[4 * k4]) =
            *reinterpret_cast<const float4*>(&h3[tid * 64 + 4 * k4]);

    float o = bd2[0];
#pragma unroll 4
    for (int jj = 0; jj < 32; jj++) {
        float d = b1s[jj];
#pragma unroll
        for (int k = 0; k < 64; k++) d += hr[k] * w1[k * 32 + jj];
        o += fmaxf(d, 0.f) * w2[jj];
    }
    out[tid] = o;
}

// ---------------------------------------------------------------------------
// Launcher
// ---------------------------------------------------------------------------
extern "C" void kernel_launch(void* const* d_in, const int* in_sizes, int n_in,
                              void* d_out, int out_size)
{
    const float* x   = (const float*)d_in[0];
    const float* W1  = (const float*)d_in[1];
    const float* Uw1 = (const float*)d_in[2];
    const float* b1  = (const float*)d_in[3];
    const float* W2  = (const float*)d_in[4];
    const float* Uw2 = (const float*)d_in[5];
    const float* b2  = (const float*)d_in[6];
    const float* W3  = (const float*)d_in[7];
    const float* Uw3 = (const float*)d_in[8];
    const float* b3  = (const float*)d_in[9];
    const float* Wd1 = (const float*)d_in[10];
    const float* bd1 = (const float*)d_in[11];
    const float* Wd2 = (const float*)d_in[12];
    const float* bd2 = (const float*)d_in[13];

    float *zx1, *h1, *zx2, *h2, *zx3, *h3;
    cudaGetSymbolAddress((void**)&zx1, g_zx1);
    cudaGetSymbolAddress((void**)&h1,  g_h1);
    cudaGetSymbolAddress((void**)&zx2, g_zx2);
    cudaGetSymbolAddress((void**)&h2,  g_h2);
    cudaGetSymbolAddress((void**)&zx3, g_zx3);
    cudaGetSymbolAddress((void**)&h3,  g_h3);

    // Layer 1
    proj_gemm<64, 512, true ><<<dim3(1024, 4), 256>>>(x,  W1, b1, zx1);
    lstm1_rec<<<128, 256>>>(zx1, Uw1, h1);
    // Layer 2
    proj_gemm<128, 256, false><<<dim3(1024, 2), 256>>>(h1, W2, b2, zx2);
    lstm64_rec<true ><<<128, 256>>>(zx2, Uw2, h2);
    // Layer 3 (only last hidden step needed)
    proj_gemm<64, 256, false><<<dim3(1024, 2), 256>>>(h2, W3, b3, zx3);
    lstm64_rec<false><<<128, 256>>>(zx3, Uw3, h3);
    // Dense head
    dense_kernel<<<1, 256>>>(h3, Wd1, bd1, Wd2, bd2, (float*)d_out);
}